// round 15
// baseline (speedup 1.0000x reference)
#include <cuda_runtime.h>
#include <cstdint>
#include <cstddef>

// Problem constants
#define B_TOT  131072
#define T_DIM  5
#define V_DIM  60
#define TV     300
#define KB     32                 // b-rows per k-tile
#define NC     296                // CTAs
#define NTILES (B_TOT / KB)       // 4096
#define NCOPY  8                  // spread accumulator copies

// Spread cross-CTA accumulators: g_red[c][j*60+v] = M[v][j] partial, c = cta&7.
// Zero-initialized at load; the last CTA re-zeroes after consuming -> invariant
// holds across graph replays.
__device__ float g_red[NCOPY][3600];
__device__ int   g_done;          // zero-init; last CTA resets to 0

// Packed f32x2 FMA (sm_100+); scalar fallback otherwise. Same numerics (.rn).
__device__ __forceinline__ unsigned long long fma2(unsigned long long a,
                                                   unsigned long long b,
                                                   unsigned long long c) {
#if defined(__CUDA_ARCH__) && (__CUDA_ARCH__ >= 1000)
    unsigned long long d;
    asm("fma.rn.f32x2 %0, %1, %2, %3;" : "=l"(d) : "l"(a), "l"(b), "l"(c));
    return d;
#else
    float2 fa = *reinterpret_cast<float2*>(&a);
    float2 fb = *reinterpret_cast<float2*>(&b);
    float2 fc = *reinterpret_cast<float2*>(&c);
    float2 fd;
    fd.x = fmaf(fa.x, fb.x, fc.x);
    fd.y = fmaf(fa.y, fb.y, fc.y);
    return *reinterpret_cast<unsigned long long*>(&fd);
#endif
}

// {f, f} packed into a 64-bit register pair
__device__ __forceinline__ unsigned long long dup2(float f) {
    unsigned long long r;
    asm("mov.b64 %0, {%1, %2};" : "=l"(r) : "f"(f), "f"(f));
    return r;
}

// ============================================================================
// Single fused kernel. GEMM core = proven R11 config (thread tile 8v x 4j,
// f32x2 pairs along v, static smem 33.4 KB, 3 CTAs/SM, KB=32 double-buffered,
// one barrier per tile). Epilogue: spread atomics -> threadfence-reduction;
// the LAST CTA computes the full 60x60 sigmoid/softmax chain and writes out.
// ============================================================================
__global__ __launch_bounds__(256, 3)
void k1_fused(const float* __restrict__ x,
              const float* __restrict__ W1,
              const float* __restrict__ W2,
              const float* __restrict__ W3,
              const float* __restrict__ b_s,
              const float* __restrict__ V_s,
              float* __restrict__ out) {
    __shared__ float sA[2][KB * 64];   // plain a  (16 KB)
    __shared__ float sR[2][KB * 68];   // plain r  (17.4 KB)
    __shared__ int   isLast;
    __shared__ float mcol[64], scol[64];

    const int tid = threadIdx.x;

    float w1[T_DIM], w3[T_DIM];
#pragma unroll
    for (int t = 0; t < T_DIM; t++) { w1[t] = W1[t]; w3[t] = W3[t]; }

    // Phase-B mapping: 2 k-groups x (8 ty x 16 tx); tile 8v x 4j per thread
    const int grp = tid >> 7;
    const int gt  = tid & 127;
    const int ty  = gt >> 4;         // v = ty*8 + 2*vp + {0,1}
    const int tx  = gt & 15;         // j = tx*4 + jj

    // Phase-A mapping: 16 b-rows x 16 v-lanes (lane 15 = zero pad), 2 passes
    const int rowA  = tid >> 4;
    const int laneA = tid & 15;

    unsigned long long acc[4][4];
#pragma unroll
    for (int vp = 0; vp < 4; vp++)
#pragma unroll
        for (int jj = 0; jj < 4; jj++) acc[vp][jj] = 0ull;

    auto phaseA = [&](int tile, int buf) {
#pragma unroll
        for (int p = 0; p < 2; p++) {
            const int k = rowA + 16 * p;
            float4 a4 = make_float4(0.f, 0.f, 0.f, 0.f);
            float4 r4 = make_float4(0.f, 0.f, 0.f, 0.f);
            if (laneA < 15) {
                const float* xb = x + (size_t)(tile * KB + k) * TV + laneA * 4;
#pragma unroll
                for (int t = 0; t < T_DIM; t++) {
                    float4 xv = *(const float4*)(xb + t * V_DIM);
                    a4.x = fmaf(xv.x, w1[t], a4.x); r4.x = fmaf(xv.x, w3[t], r4.x);
                    a4.y = fmaf(xv.y, w1[t], a4.y); r4.y = fmaf(xv.y, w3[t], r4.y);
                    a4.z = fmaf(xv.z, w1[t], a4.z); r4.z = fmaf(xv.z, w3[t], r4.z);
                    a4.w = fmaf(xv.w, w1[t], a4.w); r4.w = fmaf(xv.w, w3[t], r4.w);
                }
            }
            *(float4*)&sA[buf][k * 64 + laneA * 4] = a4;
            *(float4*)&sR[buf][k * 68 + laneA * 4] = r4;
        }
    };

    phaseA(blockIdx.x, 0);
    __syncthreads();

    int buf = 0;
    for (int tile = blockIdx.x; tile < NTILES; tile += NC) {
#pragma unroll
        for (int kk = 0; kk < KB / 2; kk++) {
            const int k = grp + kk * 2;
            const ulonglong2* pa = (const ulonglong2*)&sA[buf][k * 64 + ty * 8];
            ulonglong2 a01 = pa[0];
            ulonglong2 a23 = pa[1];
            unsigned long long ap[4] = { a01.x, a01.y, a23.x, a23.y };
            float4 r4 = *(const float4*)&sR[buf][k * 68 + tx * 4];
            unsigned long long rp[4] = { dup2(r4.x), dup2(r4.y),
                                         dup2(r4.z), dup2(r4.w) };
#pragma unroll
            for (int vp = 0; vp < 4; vp++)
#pragma unroll
                for (int jj = 0; jj < 4; jj++)
                    acc[vp][jj] = fma2(ap[vp], rp[jj], acc[vp][jj]);
        }
        const int nxt = tile + NC;
        if (nxt < NTILES) phaseA(nxt, buf ^ 1);
        __syncthreads();
        buf ^= 1;
    }

    // ---------- Reduce the 2 k-groups into Ms (sA contiguous: 64x64) -------
    float* Ms = &sA[0][0];
    if (grp == 0) {
#pragma unroll
        for (int vp = 0; vp < 4; vp++)
#pragma unroll
            for (int jj = 0; jj < 4; jj++) {
                unsigned int lo, hi;
                asm("mov.b64 {%0,%1}, %2;" : "=r"(lo), "=r"(hi) : "l"(acc[vp][jj]));
                const int v = ty * 8 + vp * 2;
                const int j = tx * 4 + jj;
                Ms[v * 64 + j]       = __uint_as_float(lo);
                Ms[(v + 1) * 64 + j] = __uint_as_float(hi);
            }
    }
    __syncthreads();
    if (grp == 1) {
#pragma unroll
        for (int vp = 0; vp < 4; vp++)
#pragma unroll
            for (int jj = 0; jj < 4; jj++) {
                unsigned int lo, hi;
                asm("mov.b64 {%0,%1}, %2;" : "=r"(lo), "=r"(hi) : "l"(acc[vp][jj]));
                const int v = ty * 8 + vp * 2;
                const int j = tx * 4 + jj;
                Ms[v * 64 + j]       += __uint_as_float(lo);
                Ms[(v + 1) * 64 + j] += __uint_as_float(hi);
            }
    }
    __syncthreads();

    // ---------- Spread atomic accumulation: g_red[c][j*60+v] += M[v][j] ----
    float* red = g_red[blockIdx.x & (NCOPY - 1)];
    for (int e = tid; e < 3600; e += 256) {
        const int j = e / 60;
        const int v = e - j * 60;
        atomicAdd(&red[e], Ms[v * 64 + j]);
    }

    // ---------- Threadfence reduction: last CTA does the epilogue ----------
    if (tid == 0) {
        __threadfence();                       // release our g_red updates
        int prev = atomicAdd(&g_done, 1);
        isLast = (prev == NC - 1) ? 1 : 0;
    }
    __syncthreads();
    if (!isLast) return;
    __threadfence();                           // acquire all CTAs' updates

    // Scratch overlays (GEMM smem is dead now):
    float* sM = &sA[0][0];   // 3600 of 4096 floats
    float* sW = &sR[0][0];   // 3600 of 4352 floats

    // Stage 1: sM[v*60+j] = sum_c g_red[c][j*60+v]; zero g_red for next call.
    for (int e = tid; e < 3600; e += 256) {
        const int j = e / 60;
        const int v = e - j * 60;
        float s = 0.f;
#pragma unroll
        for (int c = 0; c < NCOPY; c++) { s += g_red[c][e]; g_red[c][e] = 0.f; }
        sM[v * 60 + j] = s;
        sW[e] = W2[e];                          // stage-2 operand, coalesced
    }
    if (tid == 0) g_done = 0;
    __syncthreads();

    // Stage 2: sig[k][j] = sigmoid( sum_v W2[v,k]*M[v][j] + b_s[k,j] )
    float sigv[15];
#pragma unroll
    for (int it = 0; it < 15; it++) {
        const int e = tid + it * 256;           // e = k*60 + j, e < 3840
        float sg = 0.f;
        if (e < 3600) {
            const int k = e / 60;
            const int j = e - k * 60;
            float pr = 0.f;
#pragma unroll 4
            for (int v = 0; v < 60; v++)
                pr = fmaf(sW[v * 60 + k], sM[v * 60 + j], pr);
            pr += b_s[e];
            sg = 1.f / (1.f + expf(-pr));
        }
        sigv[it] = sg;
    }
    __syncthreads();
#pragma unroll
    for (int it = 0; it < 15; it++) {
        const int e = tid + it * 256;
        if (e < 3600) sM[e] = sigv[it];         // sM now holds sig[k][j]
    }
    __syncthreads();

    // Stage 3: S[i][j] = sum_k V_s[i,k] * sig[k][j]  -> sW
#pragma unroll
    for (int it = 0; it < 15; it++) {
        const int e = tid + it * 256;           // e = i*60 + j
        if (e < 3600) {
            const int i = e / 60;
            const int j = e - i * 60;
            const float* vrow = V_s + i * 60;
            float S = 0.f;
#pragma unroll 4
            for (int k = 0; k < 60; k++)
                S = fmaf(vrow[k], sM[k * 60 + j], S);
            sW[e] = S;
        }
    }
    __syncthreads();

    // Stage 4: column softmax over i.
    if (tid < 60) {
        const int j = tid;
        float m = -1e30f;
#pragma unroll 4
        for (int i = 0; i < 60; i++) m = fmaxf(m, sW[i * 60 + j]);
        float sum = 0.f;
#pragma unroll 4
        for (int i = 0; i < 60; i++) sum += expf(sW[i * 60 + j] - m);
        mcol[j] = m;
        scol[j] = 1.f / sum;
    }
    __syncthreads();

#pragma unroll
    for (int it = 0; it < 15; it++) {
        const int e = tid + it * 256;           // e = i*60 + j
        if (e < 3600) {
            const int j = e % 60;
            out[e] = expf(sW[e] - mcol[j]) * scol[j];
        }
    }
}

// ============================================================================
extern "C" void kernel_launch(void* const* d_in, const int* in_sizes, int n_in,
                              void* d_out, int out_size) {
    const float* x   = (const float*)d_in[0];
    const float* W1  = (const float*)d_in[1];
    const float* W2  = (const float*)d_in[2];
    const float* W3  = (const float*)d_in[3];
    const float* b_s = (const float*)d_in[4];
    const float* V_s = (const float*)d_in[5];
    float* out = (float*)d_out;

    k1_fused<<<NC, 256>>>(x, W1, W2, W3, b_s, V_s, out);
}

// round 16
// speedup vs baseline: 1.9569x; 1.9569x over previous
#include <cuda_runtime.h>
#include <cstdint>
#include <cstddef>

// Problem constants
#define B_TOT  131072
#define T_DIM  5
#define V_DIM  60
#define TV     300
#define KB     32                 // b-rows per k-tile
#define NC     296                // CTAs
#define NTILES (B_TOT / KB)       // 4096
#define NCOPY  8                  // spread accumulator copies

// Spread cross-CTA accumulators: g_red[c][j*60+v] = M[v][j] partial, c = cta&7.
// Zero-initialized at load; k2 re-zeroes after consuming -> invariant holds
// across graph replays.
__device__ float g_red[NCOPY][3600];

// Packed f32x2 FMA (sm_100+); scalar fallback otherwise. Same numerics (.rn).
__device__ __forceinline__ unsigned long long fma2(unsigned long long a,
                                                   unsigned long long b,
                                                   unsigned long long c) {
#if defined(__CUDA_ARCH__) && (__CUDA_ARCH__ >= 1000)
    unsigned long long d;
    asm("fma.rn.f32x2 %0, %1, %2, %3;" : "=l"(d) : "l"(a), "l"(b), "l"(c));
    return d;
#else
    float2 fa = *reinterpret_cast<float2*>(&a);
    float2 fb = *reinterpret_cast<float2*>(&b);
    float2 fc = *reinterpret_cast<float2*>(&c);
    float2 fd;
    fd.x = fmaf(fa.x, fb.x, fc.x);
    fd.y = fmaf(fa.y, fb.y, fc.y);
    return *reinterpret_cast<unsigned long long*>(&fd);
#endif
}

// {f, f} packed into a 64-bit register pair
__device__ __forceinline__ unsigned long long dup2(float f) {
    unsigned long long r;
    asm("mov.b64 %0, {%1, %2};" : "=l"(r) : "f"(f), "f"(f));
    return r;
}

__device__ __forceinline__ void prefetchL2(const void* p) {
    asm volatile("prefetch.global.L2 [%0];" :: "l"(p));
}

// ============================================================================
// Kernel 1 (R13/R14 GEMM core, UNTOUCHED mainloop): thread tile 8v x 4j,
// f32x2 pairs along v; static smem 33.4 KB -> 3 CTAs/SM; KB=32 double-buffered.
// Epilogue: spread atomics into g_red[cta&7], then L2-PREFETCH of the k2
// operands (W2, b_s, V_s) so k2's loads hit L2 instead of cold DRAM.
// ============================================================================
__global__ __launch_bounds__(256, 3)
void k1_gram(const float* __restrict__ x,
             const float* __restrict__ W1,
             const float* __restrict__ W3,
             const float* __restrict__ W2,
             const float* __restrict__ b_s,
             const float* __restrict__ V_s) {
    __shared__ float sA[2][KB * 64];   // plain a  (16 KB total)
    __shared__ float sR[2][KB * 68];   // plain r, 68-float rows (17.4 KB)

    const int tid = threadIdx.x;

    float w1[T_DIM], w3[T_DIM];
#pragma unroll
    for (int t = 0; t < T_DIM; t++) { w1[t] = W1[t]; w3[t] = W3[t]; }

    // Phase-B mapping: 2 k-groups x (8 ty x 16 tx); tile 8v x 4j per thread
    const int grp = tid >> 7;        // 0..1 : handles k = grp + 2*kk
    const int gt  = tid & 127;
    const int ty  = gt >> 4;         // 0..7 : v = ty*8 + 2*vp + {0,1}
    const int tx  = gt & 15;         // 0..15: j = tx*4 + jj

    // Phase-A mapping: 16 b-rows x 16 v-lanes (lane 15 = zero pad), 2 passes
    const int rowA  = tid >> 4;      // 0..15
    const int laneA = tid & 15;      // 0..15

    unsigned long long acc[4][4];    // [vp][jj] -> 32 registers
#pragma unroll
    for (int vp = 0; vp < 4; vp++)
#pragma unroll
        for (int jj = 0; jj < 4; jj++) acc[vp][jj] = 0ull;

    auto phaseA = [&](int tile, int buf) {
#pragma unroll
        for (int p = 0; p < 2; p++) {
            const int k = rowA + 16 * p;             // 0..31
            float4 a4 = make_float4(0.f, 0.f, 0.f, 0.f);
            float4 r4 = make_float4(0.f, 0.f, 0.f, 0.f);
            if (laneA < 15) {
                const float* xb = x + (size_t)(tile * KB + k) * TV + laneA * 4;
#pragma unroll
                for (int t = 0; t < T_DIM; t++) {
                    float4 xv = *(const float4*)(xb + t * V_DIM);
                    a4.x = fmaf(xv.x, w1[t], a4.x); r4.x = fmaf(xv.x, w3[t], r4.x);
                    a4.y = fmaf(xv.y, w1[t], a4.y); r4.y = fmaf(xv.y, w3[t], r4.y);
                    a4.z = fmaf(xv.z, w1[t], a4.z); r4.z = fmaf(xv.z, w3[t], r4.z);
                    a4.w = fmaf(xv.w, w1[t], a4.w); r4.w = fmaf(xv.w, w3[t], r4.w);
                }
            }
            *(float4*)&sA[buf][k * 64 + laneA * 4] = a4;
            *(float4*)&sR[buf][k * 68 + laneA * 4] = r4;
        }
    };

    // Prologue
    phaseA(blockIdx.x, 0);
    __syncthreads();

    int buf = 0;
    for (int tile = blockIdx.x; tile < NTILES; tile += NC) {
        // ---------- Phase B on buf: 16 kk x 16 fma2 ----------
#pragma unroll
        for (int kk = 0; kk < KB / 2; kk++) {
            const int k = grp + kk * 2;
            const ulonglong2* pa = (const ulonglong2*)&sA[buf][k * 64 + ty * 8];
            ulonglong2 a01 = pa[0];              // natural {a,a+1} pairs
            ulonglong2 a23 = pa[1];
            unsigned long long ap[4] = { a01.x, a01.y, a23.x, a23.y };
            float4 r4 = *(const float4*)&sR[buf][k * 68 + tx * 4];
            unsigned long long rp[4] = { dup2(r4.x), dup2(r4.y),
                                         dup2(r4.z), dup2(r4.w) };
#pragma unroll
            for (int vp = 0; vp < 4; vp++)
#pragma unroll
                for (int jj = 0; jj < 4; jj++)
                    acc[vp][jj] = fma2(ap[vp], rp[jj], acc[vp][jj]);
        }

        // ---------- Phase A for next tile into the other buffer ----------
        const int nxt = tile + NC;
        if (nxt < NTILES) phaseA(nxt, buf ^ 1);
        __syncthreads();
        buf ^= 1;
    }

    // ---------- Reduce the 2 k-groups into Ms (sA contiguous: 64x64) -------
    float* Ms = &sA[0][0];
    if (grp == 0) {
#pragma unroll
        for (int vp = 0; vp < 4; vp++)
#pragma unroll
            for (int jj = 0; jj < 4; jj++) {
                unsigned int lo, hi;
                asm("mov.b64 {%0,%1}, %2;" : "=r"(lo), "=r"(hi) : "l"(acc[vp][jj]));
                const int v = ty * 8 + vp * 2;
                const int j = tx * 4 + jj;
                Ms[v * 64 + j]       = __uint_as_float(lo);
                Ms[(v + 1) * 64 + j] = __uint_as_float(hi);
            }
    }
    __syncthreads();
    if (grp == 1) {
#pragma unroll
        for (int vp = 0; vp < 4; vp++)
#pragma unroll
            for (int jj = 0; jj < 4; jj++) {
                unsigned int lo, hi;
                asm("mov.b64 {%0,%1}, %2;" : "=r"(lo), "=r"(hi) : "l"(acc[vp][jj]));
                const int v = ty * 8 + vp * 2;
                const int j = tx * 4 + jj;
                Ms[v * 64 + j]       += __uint_as_float(lo);
                Ms[(v + 1) * 64 + j] += __uint_as_float(hi);
            }
    }
    __syncthreads();

    // ---------- Atomic epilogue into spread copy ----------------------------
    float* red = g_red[blockIdx.x & (NCOPY - 1)];
    for (int e = tid; e < 3600; e += 256) {
        const int j = e / 60;
        const int v = e - j * 60;
        atomicAdd(&red[e], Ms[v * 64 + j]);
    }

    // ---------- L2-prefetch k2 operands (3 x 14400 B = 113 lines each) -----
    // Issued at the tail of every CTA so the lines are L2-resident when k2
    // launches, instead of cold DRAM (the measured 13.5us k2 stall).
    for (int l = tid; l < 113; l += 256) {
        prefetchL2((const char*)W2  + l * 128);
        prefetchL2((const char*)b_s + l * 128);
        prefetchL2((const char*)V_s + l * 128);
    }
}

// ============================================================================
// Kernel 2: one CTA per output column j, 64 threads. Operands are L2-hot
// (prefetched by k1). Zeroes g_red after consuming (graph-replay invariant).
// ============================================================================
__global__ __launch_bounds__(64)
void k2_epilogue(const float* __restrict__ W2,
                 const float* __restrict__ b_s,
                 const float* __restrict__ V_s,
                 float* __restrict__ out) {
    const int j   = blockIdx.x;
    const int tid = threadIdx.x;

    __shared__ float Mcol[64];
    __shared__ float sig[64];
    __shared__ float sS[64];

    float s = 0.f;
    if (tid < 60) {
#pragma unroll
        for (int c = 0; c < NCOPY; c++) s += g_red[c][j * 60 + tid];
    }
    Mcol[tid] = s;
    __syncthreads();

    // Zero for next launch (all reads of row j are done by this CTA).
    if (tid < 60) {
#pragma unroll
        for (int c = 0; c < NCOPY; c++) g_red[c][j * 60 + tid] = 0.f;
    }

    float sg = 0.f;
    if (tid < 60) {
        const int k = tid;
        float pr = 0.f;
#pragma unroll
        for (int vv = 0; vv < 60; vv += 4) {   // 4-wide MLP vs L2 latency
            float p0 = W2[(vv + 0) * 60 + k] * Mcol[vv + 0];
            float p1 = W2[(vv + 1) * 60 + k] * Mcol[vv + 1];
            float p2 = W2[(vv + 2) * 60 + k] * Mcol[vv + 2];
            float p3 = W2[(vv + 3) * 60 + k] * Mcol[vv + 3];
            pr += (p0 + p1) + (p2 + p3);
        }
        pr += b_s[k * 60 + j];
        sg = 1.f / (1.f + expf(-pr));
    }
    sig[tid] = sg;
    __syncthreads();

    float Si = 0.f;
    if (tid < 60) {
        const float4* vr = (const float4*)(V_s + tid * 60);  // 240B rows, aligned
#pragma unroll
        for (int q = 0; q < 15; q++) {
            float4 vx = vr[q];
            Si = fmaf(vx.x, sig[q * 4 + 0], Si);
            Si = fmaf(vx.y, sig[q * 4 + 1], Si);
            Si = fmaf(vx.z, sig[q * 4 + 2], Si);
            Si = fmaf(vx.w, sig[q * 4 + 3], Si);
        }
    }
    sS[tid] = (tid < 60) ? Si : -1e30f;
    __syncthreads();

    if (tid < 60) {
        float m = -1e30f;
#pragma unroll 4
        for (int i2 = 0; i2 < 60; i2++) m = fmaxf(m, sS[i2]);
        float sum = 0.f;
#pragma unroll 4
        for (int i2 = 0; i2 < 60; i2++) sum += expf(sS[i2] - m);
        out[tid * 60 + j] = expf(Si - m) / sum;
    }
}

// ============================================================================
extern "C" void kernel_launch(void* const* d_in, const int* in_sizes, int n_in,
                              void* d_out, int out_size) {
    const float* x   = (const float*)d_in[0];
    const float* W1  = (const float*)d_in[1];
    const float* W2  = (const float*)d_in[2];
    const float* W3  = (const float*)d_in[3];
    const float* b_s = (const float*)d_in[4];
    const float* V_s = (const float*)d_in[5];
    float* out = (float*)d_out;

    k1_gram<<<NC, 256>>>(x, W1, W3, W2, b_s, V_s);
    k2_epilogue<<<V_DIM, 64>>>(W2, b_s, V_s, out);
}